// round 6
// baseline (speedup 1.0000x reference)
#include <cuda_runtime.h>
#include <cstdint>

// Problem constants (match reference_code)
#define N_USER   100000
#define N_ITEM   50000
#define NTOT     150000
#define D        64
#define NNZ_CNT  4000000
#define BATCH    2048
#define NEGS     8192
#define NOUT     (BATCH + BATCH + NEGS)   // 12288
#define BM_WORDS ((NTOT + 31) / 32)       // 4688

#define FULLMASK 0xffffffffu
#define NNZ_PER_BLOCK 2048                // 256 thr * 8 nnz

// Scratch (device globals; every row we touch is re-initialized each launch,
// so graph replays are self-consistent).
__device__ float    g_acc[(size_t)NTOT * D];   // ~38.4 MB
__device__ unsigned g_bm[BM_WORDS];            // ~19 KB
__device__ int      g_rowof[NOUT];             // resolved row per output slot

// ---------------------------------------------------------------------------
// Kernel 1: clear row bitmap
// ---------------------------------------------------------------------------
__global__ void k_clear_bm()
{
    int i = blockIdx.x * blockDim.x + threadIdx.x;
    if (i < BM_WORDS) g_bm[i] = 0u;
}

// ---------------------------------------------------------------------------
// Kernel 2: mark rows, seed g_acc[row] = e0[row]/3, cache row index
// 16 threads per output row (float4 each).
// ---------------------------------------------------------------------------
__global__ void k_mark(const int* __restrict__ users,
                       const int* __restrict__ pos,
                       const int* __restrict__ neg,
                       const float* __restrict__ ue,
                       const float* __restrict__ ie)
{
    int tid = blockIdx.x * blockDim.x + threadIdx.x;
    int rowIdx = tid >> 4;
    int l16    = tid & 15;
    if (rowIdx >= NOUT) return;

    int row;
    if (rowIdx < BATCH)            row = users[rowIdx];
    else if (rowIdx < 2 * BATCH)   row = N_USER + pos[rowIdx - BATCH];
    else                           row = N_USER + neg[rowIdx - 2 * BATCH];

    if (l16 == 0) {
        atomicOr(&g_bm[row >> 5], 1u << (row & 31));
        g_rowof[rowIdx] = row;
    }

    const float* src = (row < N_USER)
                     ? (ue + (size_t)row * D)
                     : (ie + (size_t)(row - N_USER) * D);
    float4 e = reinterpret_cast<const float4*>(src)[l16];
    const float k = 1.0f / 3.0f;
    e.x *= k; e.y *= k; e.z *= k; e.w *= k;
    reinterpret_cast<float4*>(g_acc + (size_t)row * D)[l16] = e;
}

// ---------------------------------------------------------------------------
// Kernel 3: filtered SpMM with block-wide hit compaction.
// Phase A: 256 threads scan 2048 nnz (8 rows each, int4 x2), build 8-bit hit
//          mask, warp-scan + 1 shared atomic per warp, write compacted
//          (r,c,v) to smem.
// Phase B: half-warp per hit, independent iterations -> high MLP.
// ---------------------------------------------------------------------------
__global__ void k_spmm(const int*   __restrict__ rows,
                       const int*   __restrict__ cols,
                       const float* __restrict__ vals,
                       const float* __restrict__ ue,
                       const float* __restrict__ ie)
{
    __shared__ int   sh_r[NNZ_PER_BLOCK];
    __shared__ int   sh_c[NNZ_PER_BLOCK];
    __shared__ float sh_v[NNZ_PER_BLOCK];
    __shared__ int   sh_n;

    const int tid  = threadIdx.x;
    const int lane = tid & 31;
    if (tid == 0) sh_n = 0;
    __syncthreads();

    const long blkBase = (long)blockIdx.x * NNZ_PER_BLOCK;
    const long myBase  = blkBase + (long)tid * 8;

    int r[8];
    unsigned mask8 = 0;

    if (myBase < NNZ_CNT) {     // NNZ % 8 == 0: per-thread chunk all-in or all-out
        int4 a = *reinterpret_cast<const int4*>(rows + myBase);
        int4 b = *reinterpret_cast<const int4*>(rows + myBase + 4);
        r[0]=a.x; r[1]=a.y; r[2]=a.z; r[3]=a.w;
        r[4]=b.x; r[5]=b.y; r[6]=b.z; r[7]=b.w;
#pragma unroll
        for (int j = 0; j < 8; j++) {
            if ((g_bm[r[j] >> 5] >> (r[j] & 31)) & 1u) mask8 |= (1u << j);
        }
    }

    // warp inclusive scan of per-thread hit counts, one shared atomic per warp
    int cnt = __popc(mask8);
    int inc = cnt;
#pragma unroll
    for (int d = 1; d < 32; d <<= 1) {
        int n = __shfl_up_sync(FULLMASK, inc, d);
        if (lane >= d) inc += n;
    }
    int total = __shfl_sync(FULLMASK, inc, 31);
    int wbase = 0;
    if (lane == 31 && total > 0) wbase = atomicAdd(&sh_n, total);
    wbase = __shfl_sync(FULLMASK, wbase, 31);
    int myoff = wbase + inc - cnt;

    // write compacted hits
    if (mask8) {
#pragma unroll
        for (int j = 0; j < 8; j++) {
            if ((mask8 >> j) & 1u) {
                int pos = myoff + __popc(mask8 & ((1u << j) - 1u));
                sh_r[pos] = r[j];
                sh_c[pos] = cols[myBase + j];
                sh_v[pos] = vals[myBase + j];
            }
        }
    }
    __syncthreads();

    // Phase B: half-warp (16 lanes) per hit, float4 per lane
    const int nh  = sh_n;
    const int l16 = tid & 15;
#pragma unroll 2
    for (int h = tid >> 4; h < nh; h += 16) {
        int   rr = sh_r[h];
        int   cc = sh_c[h];
        float vv = sh_v[h];

        const float* src = (cc < N_USER)
                         ? (ue + (size_t)cc * D)
                         : (ie + (size_t)(cc - N_USER) * D);
        float4 e = reinterpret_cast<const float4*>(src)[l16];
        float* dst = g_acc + (size_t)rr * D + l16 * 4;
        asm volatile("red.global.add.v4.f32 [%0], {%1, %2, %3, %4};"
                     :: "l"(dst),
                        "f"(e.x * vv), "f"(e.y * vv),
                        "f"(e.z * vv), "f"(e.w * vv)
                     : "memory");
    }
}

// ---------------------------------------------------------------------------
// Kernel 4: out[j] = 0.75 * g_acc[g_rowof[j]]
// ---------------------------------------------------------------------------
__global__ void k_out(float* __restrict__ out)
{
    int tid = blockIdx.x * blockDim.x + threadIdx.x;
    int rowIdx = tid >> 4;
    int l16    = tid & 15;
    if (rowIdx >= NOUT) return;

    int row = g_rowof[rowIdx];
    float4 a = reinterpret_cast<const float4*>(g_acc + (size_t)row * D)[l16];
    a.x *= 0.75f; a.y *= 0.75f; a.z *= 0.75f; a.w *= 0.75f;
    reinterpret_cast<float4*>(out)[(size_t)rowIdx * (D / 4) + l16] = a;
}

// ---------------------------------------------------------------------------
// Launch
// ---------------------------------------------------------------------------
extern "C" void kernel_launch(void* const* d_in, const int* in_sizes, int n_in,
                              void* d_out, int out_size)
{
    const int*   users = (const int*)  d_in[0];
    const int*   pos   = (const int*)  d_in[1];
    const int*   neg   = (const int*)  d_in[2];
    const float* ue    = (const float*)d_in[5];
    const float* ie    = (const float*)d_in[6];
    const int*   arow  = (const int*)  d_in[7];
    const int*   acol  = (const int*)  d_in[8];
    const float* aval  = (const float*)d_in[9];
    float*       out   = (float*)d_out;

    k_clear_bm<<<(BM_WORDS + 255) / 256, 256>>>();

    k_mark<<<(NOUT * 16 + 255) / 256, 256>>>(users, pos, neg, ue, ie);

    {
        const int blocks = (NNZ_CNT + NNZ_PER_BLOCK - 1) / NNZ_PER_BLOCK; // 1954
        k_spmm<<<blocks, 256>>>(arow, acol, aval, ue, ie);
    }

    k_out<<<(NOUT * 16 + 255) / 256, 256>>>(out);
}